// round 4
// baseline (speedup 1.0000x reference)
#include <cuda_runtime.h>

#define N_NODES 100000
#define N_EDGES 1600000
#define CH 64
#define YCOLS 576  // 9 * 64

// Scratch (allocation-free rule: __device__ globals)
__device__ float g_y[(size_t)N_NODES * YCOLS];   // per-node per-tap features y_k = x @ W_k
__device__ float g_h1[(size_t)N_NODES * CH];     // layer-1 pre-relu output
__device__ int   g_idx[2 * N_EDGES];             // edge indices normalized to int32
__device__ int   g_is64;                         // 1 if edge_index stored as int64

// ---------------------------------------------------------------------------
// Dtype detection: jnp.int64 edge_index may actually be int32 (JAX x64 off).
// If stored as little-endian int64 with values < 2^31, every odd 32-bit word
// of the buffer is zero. Check the first 512 words.
// ---------------------------------------------------------------------------
__global__ void detect_kernel(const int* __restrict__ ei32) {
    int ok = 1;
    for (int i = threadIdx.x * 2 + 1; i < 512; i += 64)
        if (ei32[i] != 0) ok = 0;
    ok = __all_sync(0xffffffffu, ok) ? 1 : 0;
    if (threadIdx.x == 0) g_is64 = ok;
}

__global__ __launch_bounds__(256) void convert_kernel(const int* __restrict__ ei32) {
    int j = blockIdx.x * 256 + threadIdx.x;
    if (j >= 2 * N_EDGES) return;
    int is64 = g_is64;
    int v = is64 ? ei32[2 * j] : ei32[j];
    // Defensive clamp: any out-of-range index folds to node 0 rather than UB.
    g_idx[j] = ((unsigned)v < (unsigned)N_NODES) ? v : 0;
}

// ---------------------------------------------------------------------------
// Fused GEMM: y[n, k*64+c] = x[n] @ W[k]  (jt = 0..8)
//             h[n, c]      = x[n] @ root + bias  (jt = 9)
// 64x64 tiles, 4x4 register blocking.
// ---------------------------------------------------------------------------
template<bool LAYER2>
__global__ __launch_bounds__(256) void gemm_kernel(
    const float* __restrict__ Xext,
    const float* __restrict__ W9,     // [9,64,64]
    const float* __restrict__ Wroot,  // [64,64]
    const float* __restrict__ bias,   // [64]
    float* __restrict__ Hext)
{
    __shared__ float Xs[64][66];
    __shared__ float Ws[64][64];

    const float* X = LAYER2 ? g_h1 : Xext;
    float* H = LAYER2 ? Hext : g_h1;

    const int mbase = blockIdx.x * 64;
    const int jt = blockIdx.y;  // 0..8 -> W_k tap, 9 -> root

    const float* Wsrc = (jt < 9) ? (W9 + jt * 4096) : Wroot;
    for (int idx = threadIdx.x; idx < 4096; idx += 256)
        Ws[idx >> 6][idx & 63] = Wsrc[idx];

    for (int idx = threadIdx.x; idx < 4096; idx += 256) {
        int m = idx >> 6, i = idx & 63;
        int node = mbase + m;
        float v = (node < N_NODES) ? X[(size_t)node * CH + i] : 0.f;
        if (LAYER2) v = fmaxf(v, 0.f);
        Xs[m][i] = v;
    }
    __syncthreads();

    const int tx = threadIdx.x & 15, ty = threadIdx.x >> 4;
    const int m0 = ty * 4, c0 = tx * 4;
    float acc[4][4] = {};

    #pragma unroll
    for (int i = 0; i < 64; i++) {
        float4 w4 = *(const float4*)&Ws[i][c0];
        #pragma unroll
        for (int a = 0; a < 4; a++) {
            float xv = Xs[m0 + a][i];
            acc[a][0] += xv * w4.x;
            acc[a][1] += xv * w4.y;
            acc[a][2] += xv * w4.z;
            acc[a][3] += xv * w4.w;
        }
    }

    if (jt < 9) {
        #pragma unroll
        for (int a = 0; a < 4; a++) {
            int node = mbase + m0 + a;
            if (node >= N_NODES) continue;
            float4 o = make_float4(acc[a][0], acc[a][1], acc[a][2], acc[a][3]);
            *(float4*)&g_y[(size_t)node * YCOLS + jt * 64 + c0] = o;
        }
    } else {
        float4 b4 = *(const float4*)&bias[c0];
        #pragma unroll
        for (int a = 0; a < 4; a++) {
            int node = mbase + m0 + a;
            if (node >= N_NODES) continue;
            float4 o = make_float4(acc[a][0] + b4.x, acc[a][1] + b4.y,
                                   acc[a][2] + b4.z, acc[a][3] + b4.w);
            *(float4*)&H[(size_t)node * CH + c0] = o;
        }
    }
}

// ---------------------------------------------------------------------------
// Edge kernel: one warp per edge. 9 basis weights from pseudo, gather 9 rows
// of g_y[src], weighted sum, vector red.add into H[dst].
// ---------------------------------------------------------------------------
template<bool LAYER2>
__global__ __launch_bounds__(256) void edge_kernel(
    const float* __restrict__ pseudo,    // [E, 2]
    float* __restrict__ Hext)
{
    float* H = LAYER2 ? Hext : g_h1;
    const int e = blockIdx.x * 8 + (threadIdx.x >> 5);
    if (e >= N_EDGES) return;
    const int lane = threadIdx.x & 31;

    const int src = g_idx[e];
    const int dst = g_idx[N_EDGES + e];
    const float2 p = ((const float2*)pseudo)[e];
    const float u = p.x, v = p.y;

    float b0[3], b1[3];
    b0[0] = 0.5f * u * u - u + 0.5f;
    b0[1] = -u * u + u + 0.5f;
    b0[2] = 0.5f * u * u;
    b1[0] = 0.5f * v * v - v + 0.5f;
    b1[1] = -v * v + v + 0.5f;
    b1[2] = 0.5f * v * v;

    const float2* yrow = (const float2*)(g_y + (size_t)src * YCOLS) + lane;
    float accx = 0.f, accy = 0.f;
    #pragma unroll
    for (int a = 0; a < 3; a++) {
        #pragma unroll
        for (int b = 0; b < 3; b++) {
            float w = b0[a] * b1[b];
            float2 yv = yrow[(a * 3 + b) * 32];
            accx += w * yv.x;
            accy += w * yv.y;
        }
    }

    float* hp = H + (size_t)dst * CH + lane * 2;
    // Vector reduction (sm_90+): one REDG.64 instead of two REDG.32.
    asm volatile("red.global.add.v2.f32 [%0], {%1, %2};"
                 :: "l"(hp), "f"(accx), "f"(accy) : "memory");
}

__global__ void relu_kernel(float* __restrict__ p, int n) {
    int i = blockIdx.x * blockDim.x + threadIdx.x;
    if (i < n) p[i] = fmaxf(p[i], 0.f);
}

// ---------------------------------------------------------------------------
extern "C" void kernel_launch(void* const* d_in, const int* in_sizes, int n_in,
                              void* d_out, int out_size) {
    const float* x      = (const float*)d_in[0];
    const int* ei32     = (const int*)d_in[1];   // raw words; dtype detected on device
    const float* pseudo = (const float*)d_in[2];
    const float* W1     = (const float*)d_in[3];
    const float* root1  = (const float*)d_in[4];
    const float* b1     = (const float*)d_in[5];
    const float* W2     = (const float*)d_in[6];
    const float* root2  = (const float*)d_in[7];
    const float* b2     = (const float*)d_in[8];
    float* out          = (float*)d_out;

    detect_kernel<<<1, 32>>>(ei32);
    convert_kernel<<<(2 * N_EDGES + 255) / 256, 256>>>(ei32);

    dim3 ggrid((N_NODES + 63) / 64, 10);

    // Layer 1
    gemm_kernel<false><<<ggrid, 256>>>(x, W1, root1, b1, nullptr);
    edge_kernel<false><<<N_EDGES / 8, 256>>>(pseudo, nullptr);

    // Layer 2
    gemm_kernel<true><<<ggrid, 256>>>(nullptr, W2, root2, b2, out);
    edge_kernel<true><<<N_EDGES / 8, 256>>>(pseudo, out);

    relu_kernel<<<(N_NODES * CH + 255) / 256, 256>>>(out, N_NODES * CH);
}

// round 6
// speedup vs baseline: 1.8028x; 1.8028x over previous
#include <cuda_runtime.h>

#define N_NODES 100000
#define N_EDGES 1600000
#define CH 64
#define TCOLS 576               // 9 * 64
#define SCAN_B 1024
#define NSCAN_BLOCKS ((N_NODES + SCAN_B - 1) / SCAN_B)   // 98

struct __align__(16) EdgeRec {   // 64 B
    int src; int pad0; int pad1; int pad2;
    float b[9];
    float pad3; float pad4; float pad5;
};

// ------------------------- device scratch (no allocs) -----------------------
__device__ int     g_idx[2 * N_EDGES];
__device__ int     g_is64;
__device__ int     g_cnt[N_NODES];
__device__ int     g_cur[N_NODES];
__device__ int     g_row[N_NODES + 1];
__device__ int     g_bsum[NSCAN_BLOCKS];
__device__ int     g_boff[NSCAN_BLOCKS];
__device__ EdgeRec g_edges[N_EDGES];
__device__ float   g_t[(size_t)N_NODES * TCOLS];   // aggregated basis-weighted features
__device__ float   g_x2[(size_t)N_NODES * CH];     // relu(layer-1 output)

// ---------------------------------------------------------------------------
// Dtype detection (edge_index may be stored int32 despite int64 metadata)
// ---------------------------------------------------------------------------
__global__ void detect_kernel(const int* __restrict__ ei32) {
    int ok = 1;
    for (int i = threadIdx.x * 2 + 1; i < 512; i += 64)
        if (ei32[i] != 0) ok = 0;
    ok = __all_sync(0xffffffffu, ok) ? 1 : 0;
    if (threadIdx.x == 0) g_is64 = ok;
}

__global__ __launch_bounds__(256) void zero_kernel() {
    int i = blockIdx.x * 256 + threadIdx.x;
    if (i < N_NODES) { g_cnt[i] = 0; g_cur[i] = 0; }
}

// Convert indices to int32 (clamped) and histogram destinations.
__global__ __launch_bounds__(256) void convert_hist_kernel(const int* __restrict__ ei32) {
    int j = blockIdx.x * 256 + threadIdx.x;
    if (j >= 2 * N_EDGES) return;
    int is64 = g_is64;
    int v = is64 ? ei32[2 * j] : ei32[j];
    v = ((unsigned)v < (unsigned)N_NODES) ? v : 0;
    g_idx[j] = v;
    if (j >= N_EDGES) atomicAdd(&g_cnt[v], 1);
}

// --------------------------- exclusive scan (CSR) ---------------------------
__global__ __launch_bounds__(SCAN_B) void scan1_kernel() {
    __shared__ int s[SCAN_B];
    int t = threadIdx.x;
    int i = blockIdx.x * SCAN_B + t;
    int v = (i < N_NODES) ? g_cnt[i] : 0;
    s[t] = v;
    __syncthreads();
    for (int off = 1; off < SCAN_B; off <<= 1) {
        int tmp = (t >= off) ? s[t - off] : 0;
        __syncthreads();
        s[t] += tmp;
        __syncthreads();
    }
    if (i < N_NODES) g_row[i] = s[t] - v;       // exclusive
    if (t == SCAN_B - 1) g_bsum[blockIdx.x] = s[t];
}

__global__ void scan2_kernel() {
    int run = 0;
    for (int b = 0; b < NSCAN_BLOCKS; b++) { g_boff[b] = run; run += g_bsum[b]; }
    g_row[N_NODES] = N_EDGES;
}

__global__ __launch_bounds__(256) void scan3_kernel() {
    int i = blockIdx.x * 256 + threadIdx.x;
    if (i < N_NODES) g_row[i] += g_boff[i >> 10];
}

// Scatter edges into dst-sorted order; precompute 9 B-spline basis weights.
__global__ __launch_bounds__(256) void scatter_kernel(const float* __restrict__ pseudo) {
    int e = blockIdx.x * 256 + threadIdx.x;
    if (e >= N_EDGES) return;
    int src = g_idx[e];
    int dst = g_idx[N_EDGES + e];
    float2 p = ((const float2*)pseudo)[e];
    float u = p.x, v = p.y;
    float bu0 = 0.5f * u * u - u + 0.5f, bu1 = -u * u + u + 0.5f, bu2 = 0.5f * u * u;
    float bv0 = 0.5f * v * v - v + 0.5f, bv1 = -v * v + v + 0.5f, bv2 = 0.5f * v * v;

    int pos = g_row[dst] + atomicAdd(&g_cur[dst], 1);
    float4* q = (float4*)&g_edges[pos];
    int4 s4 = make_int4(src, 0, 0, 0);
    q[0] = *(float4*)&s4;
    q[1] = make_float4(bu0 * bv0, bu0 * bv1, bu0 * bv2, bu1 * bv0);
    q[2] = make_float4(bu1 * bv1, bu1 * bv2, bu2 * bv0, bu2 * bv1);
    q[3] = make_float4(bu2 * bv2, 0.f, 0.f, 0.f);
}

// ---------------------------------------------------------------------------
// Aggregation: one warp per dst node; lane owns 2 channels.
// t[node, k*64 + c] = sum_{edges e->node} B[e,k] * X[src(e), c]
// X is small (25.6 MB) -> gathers hit L2.
// ---------------------------------------------------------------------------
__global__ __launch_bounds__(256) void agg_kernel(const float* __restrict__ X) {
    int node = blockIdx.x * 8 + (threadIdx.x >> 5);
    if (node >= N_NODES) return;
    const int lane = threadIdx.x & 31;

    int beg = g_row[node], end = g_row[node + 1];
    float acc[9][2] = {};

    #pragma unroll 2
    for (int e = beg; e < end; e++) {
        const EdgeRec* r = &g_edges[e];
        int src = __ldg(&r->src);
        float4 b03 = __ldg((const float4*)&r->b[0]);
        float4 b47 = __ldg((const float4*)&r->b[4]);
        float  b8  = __ldg(&r->b[8]);
        float2 xv  = __ldg((const float2*)&X[(size_t)src * CH + 2 * lane]);
        acc[0][0] += b03.x * xv.x; acc[0][1] += b03.x * xv.y;
        acc[1][0] += b03.y * xv.x; acc[1][1] += b03.y * xv.y;
        acc[2][0] += b03.z * xv.x; acc[2][1] += b03.z * xv.y;
        acc[3][0] += b03.w * xv.x; acc[3][1] += b03.w * xv.y;
        acc[4][0] += b47.x * xv.x; acc[4][1] += b47.x * xv.y;
        acc[5][0] += b47.y * xv.x; acc[5][1] += b47.y * xv.y;
        acc[6][0] += b47.z * xv.x; acc[6][1] += b47.z * xv.y;
        acc[7][0] += b47.w * xv.x; acc[7][1] += b47.w * xv.y;
        acc[8][0] += b8    * xv.x; acc[8][1] += b8    * xv.y;
    }

    float* tp = g_t + (size_t)node * TCOLS + 2 * lane;
    #pragma unroll
    for (int k = 0; k < 9; k++) {
        float2 o = make_float2(acc[k][0], acc[k][1]);
        *(float2*)(tp + k * 64) = o;
    }
}

// ---------------------------------------------------------------------------
// Fused GEMM: out[n,c] = relu( bias[c] + t[n,:]@W9flat + X[n,:]@root )
// K = 576 (t) + 64 (x) = 640, tiled 128x64, 4x8 register blocking.
// ---------------------------------------------------------------------------
__global__ __launch_bounds__(256) void gemm_kernel(
    const float* __restrict__ X,
    const float* __restrict__ W9,     // [576,64] row-major
    const float* __restrict__ root,   // [64,64]
    const float* __restrict__ bias,   // [64]
    float* __restrict__ out)
{
    __shared__ float As[32][132];   // [kk][m], padded
    __shared__ float Bs[32][64];    // [kk][c]

    const int mbase = blockIdx.x * 128;
    const int tid = threadIdx.x;
    const int tx = tid & 15, ty = tid >> 4;   // c0 = tx*4, rows ty*8..+7
    const int f4c = tid & 7, r0 = tid >> 3;   // A-load mapping
    const int bkk = tid >> 3, bf = tid & 7;   // B-load mapping

    float acc[8][4] = {};

    for (int chunk = 0; chunk < 20; chunk++) {
        // ---- load A tile: 128 rows x 32 k ----
        #pragma unroll
        for (int pass = 0; pass < 4; pass++) {
            int r = r0 + pass * 32;
            int node = mbase + r;
            float4 v = make_float4(0.f, 0.f, 0.f, 0.f);
            if (node < N_NODES) {
                const float* src = (chunk < 18)
                    ? (g_t + (size_t)node * TCOLS + chunk * 32)
                    : (X + (size_t)node * CH + (chunk - 18) * 32);
                v = *(const float4*)(src + f4c * 4);
            }
            int kc = f4c * 4;
            As[kc + 0][r] = v.x;
            As[kc + 1][r] = v.y;
            As[kc + 2][r] = v.z;
            As[kc + 3][r] = v.w;
        }
        // ---- load B tile: 32 k x 64 c ----
        {
            int j = chunk * 32 + bkk;
            const float* wsrc = (chunk < 18) ? (W9 + (size_t)j * 64)
                                             : (root + (size_t)(j - 576) * 64);
            *(float4*)&Bs[bkk][bf * 4]        = *(const float4*)(wsrc + bf * 4);
            *(float4*)&Bs[bkk][(bf + 8) * 4]  = *(const float4*)(wsrc + (bf + 8) * 4);
        }
        __syncthreads();

        #pragma unroll
        for (int kk = 0; kk < 32; kk++) {
            float4 a0 = *(const float4*)&As[kk][ty * 8];
            float4 a1 = *(const float4*)&As[kk][ty * 8 + 4];
            float4 b4 = *(const float4*)&Bs[kk][tx * 4];
            float am[8] = {a0.x, a0.y, a0.z, a0.w, a1.x, a1.y, a1.z, a1.w};
            #pragma unroll
            for (int a = 0; a < 8; a++) {
                acc[a][0] += am[a] * b4.x;
                acc[a][1] += am[a] * b4.y;
                acc[a][2] += am[a] * b4.z;
                acc[a][3] += am[a] * b4.w;
            }
        }
        __syncthreads();
    }

    float4 b4 = *(const float4*)&bias[tx * 4];
    #pragma unroll
    for (int a = 0; a < 8; a++) {
        int node = mbase + ty * 8 + a;
        if (node >= N_NODES) continue;
        float4 o = make_float4(fmaxf(acc[a][0] + b4.x, 0.f),
                               fmaxf(acc[a][1] + b4.y, 0.f),
                               fmaxf(acc[a][2] + b4.z, 0.f),
                               fmaxf(acc[a][3] + b4.w, 0.f));
        *(float4*)&out[(size_t)node * CH + tx * 4] = o;
    }
}

// ---------------------------------------------------------------------------
extern "C" void kernel_launch(void* const* d_in, const int* in_sizes, int n_in,
                              void* d_out, int out_size) {
    const float* x      = (const float*)d_in[0];
    const int* ei32     = (const int*)d_in[1];
    const float* pseudo = (const float*)d_in[2];
    const float* W1     = (const float*)d_in[3];
    const float* root1  = (const float*)d_in[4];
    const float* b1     = (const float*)d_in[5];
    const float* W2     = (const float*)d_in[6];
    const float* root2  = (const float*)d_in[7];
    const float* b2     = (const float*)d_in[8];
    float* out          = (float*)d_out;

    // ---- build dst-sorted CSR + per-edge basis (shared by both layers) ----
    detect_kernel<<<1, 32>>>(ei32);
    zero_kernel<<<(N_NODES + 255) / 256, 256>>>();
    convert_hist_kernel<<<(2 * N_EDGES + 255) / 256, 256>>>(ei32);
    scan1_kernel<<<NSCAN_BLOCKS, SCAN_B>>>();
    scan2_kernel<<<1, 1>>>();
    scan3_kernel<<<(N_NODES + 255) / 256, 256>>>();
    scatter_kernel<<<(N_EDGES + 255) / 256, 256>>>(pseudo);

    const int agg_grid  = (N_NODES + 7) / 8;
    const int gemm_grid = (N_NODES + 127) / 128;

    // ---- layer 1 ----
    agg_kernel<<<agg_grid, 256>>>(x);
    gemm_kernel<<<gemm_grid, 256>>>(x, W1, root1, b1, g_x2);

    // ---- layer 2 ----
    agg_kernel<<<agg_grid, 256>>>(g_x2);
    gemm_kernel<<<gemm_grid, 256>>>(g_x2, W2, root2, b2, out);
}